// round 3
// baseline (speedup 1.0000x reference)
#include <cuda_runtime.h>
#include <math.h>

#define D_MODEL 1024
#define NHEADS  16
#define DK      64
#define SEQ     2048
#define BATCH   2
#define MTOT    (BATCH*SEQ)

typedef unsigned long long u64;

// ---- packed fp32x2 helpers (Blackwell 2x fp32 datapath; PTX-only) ----
__device__ __forceinline__ u64 pk2(float lo, float hi) {
    u64 r; asm("mov.b64 %0,{%1,%2};" : "=l"(r) : "f"(lo), "f"(hi)); return r;
}
__device__ __forceinline__ float2 upk2(u64 v) {
    float lo, hi; asm("mov.b64 {%0,%1},%2;" : "=f"(lo), "=f"(hi) : "l"(v));
    return make_float2(lo, hi);
}
#define FMA2(d,a,b) asm("fma.rn.f32x2 %0,%1,%2,%0;" : "+l"(d) : "l"(a), "l"(b))
#define MUL2(d,a)   asm("mul.rn.f32x2 %0,%0,%1;"    : "+l"(d) : "l"(a))

// ---- device scratch (no cudaMalloc allowed) ----
__device__ float g_Q[(size_t)BATCH*NHEADS*SEQ*DK];
__device__ float g_K[(size_t)BATCH*NHEADS*SEQ*DK];
__device__ float g_V[(size_t)BATCH*NHEADS*SEQ*DK];
__device__ float g_A[(size_t)BATCH*SEQ*D_MODEL];
__device__ float g_cos[SEQ*(DK/2)];
__device__ float g_sin[SEQ*(DK/2)];

// ---------------- RoPE table (double precision, tiny) ----------------
__global__ void rope_table_kernel() {
    int i = blockIdx.x*blockDim.x + threadIdx.x;
    if (i >= SEQ*(DK/2)) return;
    int s = i / (DK/2);
    int j = i % (DK/2);
    double freq = pow(10000.0, -(double)(2*j)/(double)DK);
    double ang  = (double)s * freq;
    g_cos[i] = (float)cos(ang);
    g_sin[i] = (float)sin(ang);
}

// fast exp2 on fma/alu pipes (avoids MUFU throughput wall)
__device__ __forceinline__ float exp2f_fast(float x) {
    x = fmaxf(x, -125.0f);
    float t = x + 12582912.0f;
    float f = x - (t - 12582912.0f);
    int   e = __float_as_int(t) << 23;
    float p = 1.5402387e-4f;
    p = fmaf(p, f, 1.3333558e-3f);
    p = fmaf(p, f, 9.6181291e-3f);
    p = fmaf(p, f, 5.5504109e-2f);
    p = fmaf(p, f, 2.4022651e-1f);
    p = fmaf(p, f, 6.9314718e-1f);
    p = fmaf(p, f, 1.0f);
    return __int_as_float(__float_as_int(p) + e);
}

// ================= shared GEMM core (128x128 tile, f32x2 inner) =================
// As: [16][132]  A^T tile (k-major rows, m columns)
// Bs2:[16][268]  B^T tile with every value DUPLICATED along n: Bs2[k][2n]=Bs2[k][2n+1]=B[n][k]
// c2[i2][j]: packed pair (c[2*i2][j], c[2*i2+1][j]); 8 m-rows x 8 n-cols per thread.
struct GemmFrag { u64 c2[4][8]; };

__device__ __forceinline__ void gemm_mainloop_128(
    const float* __restrict__ Aptr, const float* __restrict__ Bptr,
    float (*As)[132], float (*Bs2)[268],
    int tid, GemmFrag& fr)
{
    const int tx = tid & 15, ty = tid >> 4;
    const int r  = tid >> 2;
    const int c4 = (tid & 3) << 2;

    float4 a0 = *(const float4*)(Aptr);
    float4 a1 = *(const float4*)(Aptr + 64*D_MODEL);
    float4 b0 = *(const float4*)(Bptr);
    float4 b1 = *(const float4*)(Bptr + 64*D_MODEL);

    #pragma unroll
    for (int i2 = 0; i2 < 4; i2++)
        #pragma unroll
        for (int j = 0; j < 8; j++) fr.c2[i2][j] = 0ull;

    for (int k0 = 0; k0 < D_MODEL; k0 += 16) {
        As[c4+0][r]=a0.x; As[c4+1][r]=a0.y; As[c4+2][r]=a0.z; As[c4+3][r]=a0.w;
        As[c4+0][r+64]=a1.x; As[c4+1][r+64]=a1.y; As[c4+2][r+64]=a1.z; As[c4+3][r+64]=a1.w;
        *(float2*)&Bs2[c4+0][2*r] = make_float2(b0.x, b0.x);
        *(float2*)&Bs2[c4+1][2*r] = make_float2(b0.y, b0.y);
        *(float2*)&Bs2[c4+2][2*r] = make_float2(b0.z, b0.z);
        *(float2*)&Bs2[c4+3][2*r] = make_float2(b0.w, b0.w);
        *(float2*)&Bs2[c4+0][2*(r+64)] = make_float2(b1.x, b1.x);
        *(float2*)&Bs2[c4+1][2*(r+64)] = make_float2(b1.y, b1.y);
        *(float2*)&Bs2[c4+2][2*(r+64)] = make_float2(b1.z, b1.z);
        *(float2*)&Bs2[c4+3][2*(r+64)] = make_float2(b1.w, b1.w);
        __syncthreads();
        if (k0 + 16 < D_MODEL) {
            a0 = *(const float4*)(Aptr + k0 + 16);
            a1 = *(const float4*)(Aptr + 64*D_MODEL + k0 + 16);
            b0 = *(const float4*)(Bptr + k0 + 16);
            b1 = *(const float4*)(Bptr + 64*D_MODEL + k0 + 16);
        }
        #pragma unroll
        for (int kk = 0; kk < 16; kk++) {
            ulonglong2 aA = *(const ulonglong2*)&As[kk][ty*8];
            ulonglong2 aB = *(const ulonglong2*)&As[kk][ty*8+4];
            u64 ap[4] = {aA.x, aA.y, aB.x, aB.y};
            ulonglong2 bA = *(const ulonglong2*)&Bs2[kk][tx*16];
            ulonglong2 bB = *(const ulonglong2*)&Bs2[kk][tx*16+4];
            ulonglong2 bC = *(const ulonglong2*)&Bs2[kk][tx*16+8];
            ulonglong2 bD = *(const ulonglong2*)&Bs2[kk][tx*16+12];
            u64 bd[8] = {bA.x, bA.y, bB.x, bB.y, bC.x, bC.y, bD.x, bD.y};
            #pragma unroll
            for (int i2 = 0; i2 < 4; i2++)
                #pragma unroll
                for (int j = 0; j < 8; j++)
                    FMA2(fr.c2[i2][j], ap[i2], bd[j]);
        }
        __syncthreads();
    }
}

// ---------------- fused QKV GEMM + RoPE epilogue ----------------
__global__ __launch_bounds__(256,2) void qkv_gemm_kernel(
    const float* __restrict__ x,
    const float* __restrict__ Wq,
    const float* __restrict__ Wk,
    const float* __restrict__ Wv)
{
    __shared__ float As[16][132];
    __shared__ float Bs2[16][268];
    const int z = blockIdx.z;
    const float* __restrict__ W = (z==0) ? Wq : ((z==1) ? Wk : Wv);
    const int tid = threadIdx.x;
    const int tx = tid & 15, ty = tid >> 4;
    const int m0 = blockIdx.y * 128;
    const int n0 = blockIdx.x * 128;
    const int r  = tid >> 2;
    const int c4 = (tid & 3) << 2;

    GemmFrag fr;
    gemm_mainloop_128(x + (size_t)(m0 + r)*D_MODEL + c4,
                      W + (size_t)(n0 + r)*D_MODEL + c4,
                      As, Bs2, tid, fr);

    const int n_base = n0 + tx*8;
    const int h = n_base >> 6;
    const int d = n_base & 63;
    #pragma unroll
    for (int i2 = 0; i2 < 4; i2++) {
        float crow[2][8];
        #pragma unroll
        for (int j = 0; j < 8; j++) {
            float2 p = upk2(fr.c2[i2][j]);
            crow[0][j] = p.x; crow[1][j] = p.y;
        }
        #pragma unroll
        for (int hh = 0; hh < 2; hh++) {
            int m = m0 + ty*8 + 2*i2 + hh;
            int b = m >> 11, s = m & (SEQ-1);
            if (z < 2) {
                float* out = (z==0) ? g_Q : g_K;
                const float* cs = g_cos + s*(DK/2) + (d>>1);
                const float* sn = g_sin + s*(DK/2) + (d>>1);
                float o[8];
                #pragma unroll
                for (int j = 0; j < 8; j += 2) {
                    float cv = cs[j>>1], sv = sn[j>>1];
                    o[j]   = cv*crow[hh][j] - sv*crow[hh][j+1];
                    o[j+1] = sv*crow[hh][j] + cv*crow[hh][j+1];
                }
                float* dst = out + (((size_t)(b*NHEADS+h))*SEQ + s)*DK + d;
                *(float4*)(dst)   = make_float4(o[0],o[1],o[2],o[3]);
                *(float4*)(dst+4) = make_float4(o[4],o[5],o[6],o[7]);
            } else {
                float* dst = g_V + (((size_t)(b*NHEADS+h))*SEQ + s)*DK + d;
                *(float4*)(dst)   = make_float4(crow[hh][0],crow[hh][1],crow[hh][2],crow[hh][3]);
                *(float4*)(dst+4) = make_float4(crow[hh][4],crow[hh][5],crow[hh][6],crow[hh][7]);
            }
        }
    }
}

// ---------------- output projection ----------------
__global__ __launch_bounds__(256,2) void out_gemm_kernel(
    const float* __restrict__ Wo, float* __restrict__ out)
{
    __shared__ float As[16][132];
    __shared__ float Bs2[16][268];
    const int tid = threadIdx.x;
    const int tx = tid & 15, ty = tid >> 4;
    const int m0 = blockIdx.y * 128;
    const int n0 = blockIdx.x * 128;
    const int r  = tid >> 2;
    const int c4 = (tid & 3) << 2;

    GemmFrag fr;
    gemm_mainloop_128(g_A + (size_t)(m0 + r)*D_MODEL + c4,
                      Wo  + (size_t)(n0 + r)*D_MODEL + c4,
                      As, Bs2, tid, fr);

    #pragma unroll
    for (int i2 = 0; i2 < 4; i2++) {
        float crow[2][8];
        #pragma unroll
        for (int j = 0; j < 8; j++) {
            float2 p = upk2(fr.c2[i2][j]);
            crow[0][j] = p.x; crow[1][j] = p.y;
        }
        #pragma unroll
        for (int hh = 0; hh < 2; hh++) {
            int m = m0 + ty*8 + 2*i2 + hh;
            float* dst = out + (size_t)m*D_MODEL + n0 + tx*8;
            *(float4*)(dst)   = make_float4(crow[hh][0],crow[hh][1],crow[hh][2],crow[hh][3]);
            *(float4*)(dst+4) = make_float4(crow[hh][4],crow[hh][5],crow[hh][6],crow[hh][7]);
        }
    }
}

// ---------------- flash attention (causal, fp32, f32x2 inner) ----------------
// BM=128 queries, BN=64 keys, 256 threads, 8x4 micro-tile.
// Qs : [d=64][row 128+4]           (q-rows contiguous -> free a-pairs)
// Ks2: [d=64][2*col 128+4]         (k-values duplicated -> free dup-pairs)
// Vs2: [k=64][2*col 128+4]         (v-values duplicated)
// Ps : [k=64][row 128+4]           (p rows contiguous -> free a-pairs)
__global__ __launch_bounds__(256,1) void flash_kernel()
{
    extern __shared__ float sm[];
    float (*Qs)[132]  = (float(*)[132])(sm);
    float (*Ks2)[132] = (float(*)[132])(sm + 64*132);
    float (*Vs2)[132] = (float(*)[132])(sm + 2*64*132);
    float (*Ps)[132]  = (float(*)[132])(sm + 3*64*132);

    const int tid = threadIdx.x;
    const int tx = tid & 15, ty = tid >> 4;
    const int qt = gridDim.x - 1 - blockIdx.x;   // long blocks first
    const int bh = blockIdx.y;
    const int b  = bh >> 4, h = bh & 15;

    const float* __restrict__ Qg = g_Q + (size_t)bh*SEQ*DK;
    const float* __restrict__ Kg = g_K + (size_t)bh*SEQ*DK;
    const float* __restrict__ Vg = g_V + (size_t)bh*SEQ*DK;

    #pragma unroll
    for (int it = 0; it < 8; it++) {
        int idx = tid + it*256;
        int rq = idx >> 4, c4 = (idx & 15) << 2;
        float4 v = *(const float4*)(Qg + (size_t)(qt*128 + rq)*DK + c4);
        Qs[c4+0][rq]=v.x; Qs[c4+1][rq]=v.y; Qs[c4+2][rq]=v.z; Qs[c4+3][rq]=v.w;
    }

    u64 o2[4][4];
    #pragma unroll
    for (int i2 = 0; i2 < 4; i2++)
        #pragma unroll
        for (int j = 0; j < 4; j++) o2[i2][j] = 0ull;
    float m_i[8], l_i[8];
    #pragma unroll
    for (int i = 0; i < 8; i++) { m_i[i] = -1e30f; l_i[i] = 0.f; }

    const float SC = 0.18033688011112042f;  // log2(e)/sqrt(64)
    const int ktmax = 2*qt + 1;

    for (int kt = 0; kt <= ktmax; kt++) {
        __syncthreads();
        #pragma unroll
        for (int it = 0; it < 4; it++) {
            int idx = tid + it*256;
            int rk = idx >> 4, c4 = (idx & 15) << 2;
            float4 kv = *(const float4*)(Kg + (size_t)(kt*64 + rk)*DK + c4);
            *(float2*)&Ks2[c4+0][2*rk] = make_float2(kv.x, kv.x);
            *(float2*)&Ks2[c4+1][2*rk] = make_float2(kv.y, kv.y);
            *(float2*)&Ks2[c4+2][2*rk] = make_float2(kv.z, kv.z);
            *(float2*)&Ks2[c4+3][2*rk] = make_float2(kv.w, kv.w);
            float4 vv = *(const float4*)(Vg + (size_t)(kt*64 + rk)*DK + c4);
            *(float2*)&Vs2[rk][2*(c4+0)] = make_float2(vv.x, vv.x);
            *(float2*)&Vs2[rk][2*(c4+1)] = make_float2(vv.y, vv.y);
            *(float2*)&Vs2[rk][2*(c4+2)] = make_float2(vv.z, vv.z);
            *(float2*)&Vs2[rk][2*(c4+3)] = make_float2(vv.w, vv.w);
        }
        __syncthreads();

        u64 s2[4][4];
        #pragma unroll
        for (int i2 = 0; i2 < 4; i2++)
            #pragma unroll
            for (int j = 0; j < 4; j++) s2[i2][j] = 0ull;

        #pragma unroll 8
        for (int d = 0; d < 64; d++) {
            ulonglong2 qA = *(const ulonglong2*)&Qs[d][ty*8];
            ulonglong2 qB = *(const ulonglong2*)&Qs[d][ty*8+4];
            u64 qp[4] = {qA.x, qA.y, qB.x, qB.y};
            ulonglong2 kA = *(const ulonglong2*)&Ks2[d][tx*8];
            ulonglong2 kB = *(const ulonglong2*)&Ks2[d][tx*8+4];
            u64 kd[4] = {kA.x, kA.y, kB.x, kB.y};
            #pragma unroll
            for (int i2 = 0; i2 < 4; i2++)
                #pragma unroll
                for (int j = 0; j < 4; j++)
                    FMA2(s2[i2][j], qp[i2], kd[j]);
        }

        float s_[8][4];
        #pragma unroll
        for (int i2 = 0; i2 < 4; i2++)
            #pragma unroll
            for (int j = 0; j < 4; j++) {
                float2 p = upk2(s2[i2][j]);
                s_[2*i2][j] = p.x; s_[2*i2+1][j] = p.y;
            }

        if (kt >= 2*qt) {
            #pragma unroll
            for (int i = 0; i < 8; i++) {
                int qi = qt*128 + ty*8 + i;
                #pragma unroll
                for (int j = 0; j < 4; j++) {
                    int kj = kt*64 + tx*4 + j;
                    s_[i][j] = (kj <= qi) ? s_[i][j]*SC : -1e30f;
                }
            }
        } else {
            #pragma unroll
            for (int i = 0; i < 8; i++)
                #pragma unroll
                for (int j = 0; j < 4; j++)
                    s_[i][j] *= SC;
        }

        float corr[8];
        #pragma unroll
        for (int i = 0; i < 8; i++) {
            float mx = fmaxf(fmaxf(s_[i][0],s_[i][1]), fmaxf(s_[i][2],s_[i][3]));
            #pragma unroll
            for (int off = 8; off >= 1; off >>= 1)
                mx = fmaxf(mx, __shfl_xor_sync(0xffffffffu, mx, off, 16));
            float mnew = fmaxf(m_i[i], mx);
            float p[4], rs = 0.f;
            #pragma unroll
            for (int j = 0; j < 4; j++) { p[j] = exp2f_fast(s_[i][j] - mnew); rs += p[j]; }
            #pragma unroll
            for (int off = 8; off >= 1; off >>= 1)
                rs += __shfl_xor_sync(0xffffffffu, rs, off, 16);
            corr[i] = exp2f_fast(m_i[i] - mnew);
            l_i[i] = l_i[i]*corr[i] + rs;
            m_i[i] = mnew;
            #pragma unroll
            for (int j = 0; j < 4; j++)
                Ps[tx*4+j][ty*8+i] = p[j];
        }
        #pragma unroll
        for (int i2 = 0; i2 < 4; i2++) {
            u64 c2 = pk2(corr[2*i2], corr[2*i2+1]);
            #pragma unroll
            for (int j = 0; j < 4; j++)
                MUL2(o2[i2][j], c2);
        }
        __syncthreads();

        #pragma unroll 8
        for (int k = 0; k < 64; k++) {
            ulonglong2 pA = *(const ulonglong2*)&Ps[k][ty*8];
            ulonglong2 pB = *(const ulonglong2*)&Ps[k][ty*8+4];
            u64 pp[4] = {pA.x, pA.y, pB.x, pB.y};
            ulonglong2 vA = *(const ulonglong2*)&Vs2[k][tx*8];
            ulonglong2 vB = *(const ulonglong2*)&Vs2[k][tx*8+4];
            u64 vd[4] = {vA.x, vA.y, vB.x, vB.y};
            #pragma unroll
            for (int i2 = 0; i2 < 4; i2++)
                #pragma unroll
                for (int j = 0; j < 4; j++)
                    FMA2(o2[i2][j], pp[i2], vd[j]);
        }
    }

    #pragma unroll
    for (int i2 = 0; i2 < 4; i2++) {
        float orow[2][4];
        #pragma unroll
        for (int j = 0; j < 4; j++) {
            float2 p = upk2(o2[i2][j]);
            orow[0][j] = p.x; orow[1][j] = p.y;
        }
        #pragma unroll
        for (int hh = 0; hh < 2; hh++) {
            int i = 2*i2 + hh;
            float inv = 1.0f / l_i[i];
            int s_idx = qt*128 + ty*8 + i;
            float4 val = make_float4(orow[hh][0]*inv, orow[hh][1]*inv,
                                     orow[hh][2]*inv, orow[hh][3]*inv);
            *(float4*)(g_A + ((size_t)b*SEQ + s_idx)*D_MODEL + h*DK + tx*4) = val;
        }
    }
}

// ---------------- launch ----------------
extern "C" void kernel_launch(void* const* d_in, const int* in_sizes, int n_in,
                              void* d_out, int out_size)
{
    const float* x  = (const float*)d_in[0];
    const float* Wq = (const float*)d_in[1];
    const float* Wk = (const float*)d_in[2];
    const float* Wv = (const float*)d_in[3];
    const float* Wo = (const float*)d_in[4];
    float* out = (float*)d_out;

    const int flash_smem = 4*64*132*sizeof(float);   // 135168 B
    cudaFuncSetAttribute(flash_kernel, cudaFuncAttributeMaxDynamicSharedMemorySize, flash_smem);

    rope_table_kernel<<<(SEQ*(DK/2) + 255)/256, 256>>>();

    dim3 g1(D_MODEL/128, MTOT/128, 3);
    qkv_gemm_kernel<<<g1, 256>>>(x, Wq, Wk, Wv);

    dim3 g2(SEQ/128, BATCH*NHEADS);
    flash_kernel<<<g2, 256, flash_smem>>>();

    dim3 g3(D_MODEL/128, MTOT/128, 1);
    out_gemm_kernel<<<g3, 256>>>(Wo, out);
}

// round 5
// speedup vs baseline: 2.9267x; 2.9267x over previous
#include <cuda_runtime.h>
#include <cuda_bf16.h>
#include <cstdint>
#include <math.h>

#define D_MODEL 1024
#define NHEADS  16
#define DK      64
#define SEQ     2048
#define BATCH   2
#define MTOT    (BATCH*SEQ)

// ---- device scratch (no cudaMalloc allowed) ----
__device__ float g_Q[(size_t)BATCH*NHEADS*SEQ*DK];
__device__ float g_K[(size_t)BATCH*NHEADS*SEQ*DK];
__device__ float g_V[(size_t)BATCH*NHEADS*SEQ*DK];
__device__ float g_A[(size_t)BATCH*SEQ*D_MODEL];
__device__ float g_cos[SEQ*(DK/2)];
__device__ float g_sin[SEQ*(DK/2)];

// =============== helpers ===============
__device__ __forceinline__ uint32_t smem_u32(const void* p) {
    uint32_t a;
    asm("{ .reg .u64 t; cvta.to.shared.u64 t, %1; cvt.u32.u64 %0, t; }" : "=r"(a) : "l"(p));
    return a;
}
__device__ __forceinline__ void ldsm4(uint32_t* r, uint32_t a) {
    asm volatile("ldmatrix.sync.aligned.m8n8.x4.shared.b16 {%0,%1,%2,%3}, [%4];"
        : "=r"(r[0]), "=r"(r[1]), "=r"(r[2]), "=r"(r[3]) : "r"(a));
}
__device__ __forceinline__ void mma16816(float* d, const uint32_t* a, uint32_t b0, uint32_t b1) {
    asm volatile("mma.sync.aligned.m16n8k16.row.col.f32.bf16.bf16.f32 "
        "{%0,%1,%2,%3},{%4,%5,%6,%7},{%8,%9},{%0,%1,%2,%3};"
        : "+f"(d[0]), "+f"(d[1]), "+f"(d[2]), "+f"(d[3])
        : "r"(a[0]), "r"(a[1]), "r"(a[2]), "r"(a[3]), "r"(b0), "r"(b1));
}

// ---------------- RoPE table ----------------
__global__ void rope_table_kernel() {
    int i = blockIdx.x*blockDim.x + threadIdx.x;
    if (i >= SEQ*(DK/2)) return;
    int s = i / (DK/2);
    int j = i % (DK/2);
    double freq = pow(10000.0, -(double)(2*j)/(double)DK);
    double ang  = (double)s * freq;
    g_cos[i] = (float)cos(ang);
    g_sin[i] = (float)sin(ang);
}

__device__ __forceinline__ float exp2f_fast(float x) {
    x = fmaxf(x, -125.0f);
    float t = x + 12582912.0f;
    float f = x - (t - 12582912.0f);
    int   e = __float_as_int(t) << 23;
    float p = 1.5402387e-4f;
    p = fmaf(p, f, 1.3333558e-3f);
    p = fmaf(p, f, 9.6181291e-3f);
    p = fmaf(p, f, 5.5504109e-2f);
    p = fmaf(p, f, 2.4022651e-1f);
    p = fmaf(p, f, 6.9314718e-1f);
    p = fmaf(p, f, 1.0f);
    return __int_as_float(__float_as_int(p) + e);
}

// =============== bf16 3-split GEMM core (mma.sync HMMA path) ===============
// CTA tile 128x128, 8 warps (4m x 2n), warp tile 32x64, K in 32-chunks, 2 stages.
// Stage layout (bytes, 80B row stride = conflict-free for ldmatrix):
//   Ah @ 0, Al @ 10240, Bh @ 20480, Bl @ 30720 ; stage size 40960.
#define STG_SZ 40960u
#define AL_OFF 10240u
#define BH_OFF 20480u
#define BL_OFF 30720u

__device__ __forceinline__ void pack_store(char* dst_h, char* dst_l, const float* f) {
    uint32_t H[8], L[8];
    #pragma unroll
    for (int i = 0; i < 8; i++) {
        float f0 = f[2*i], f1 = f[2*i+1];
        __nv_bfloat162 h2 = __floats2bfloat162_rn(f0, f1);
        float r0 = f0 - __low2float(h2);
        float r1 = f1 - __high2float(h2);
        __nv_bfloat162 l2 = __floats2bfloat162_rn(r0, r1);
        H[i] = *(uint32_t*)&h2;
        L[i] = *(uint32_t*)&l2;
    }
    *(uint4*)(dst_h)      = make_uint4(H[0], H[1], H[2], H[3]);
    *(uint4*)(dst_h + 16) = make_uint4(H[4], H[5], H[6], H[7]);
    *(uint4*)(dst_l)      = make_uint4(L[0], L[1], L[2], L[3]);
    *(uint4*)(dst_l + 16) = make_uint4(L[4], L[5], L[6], L[7]);
}

__device__ __forceinline__ void bf16_gemm_core(
    const float* __restrict__ Ag, const float* __restrict__ Bg,
    char* sm, int tid, float acc[2][8][4])
{
    const int lane = tid & 31, warp = tid >> 5;
    const int wm = warp & 3, wn = warp >> 2;
    const int lr = tid >> 1;           // 0..127 (row)
    const int lc = (tid & 1) * 16;     // 0 or 16 (col within 32-chunk)
    const uint32_t sbase = smem_u32(sm);

    const uint32_t a_off = (uint32_t)(wm*32 + (lane & 15))*80u + (uint32_t)((lane >> 4)*16);
    const uint32_t b_off = (uint32_t)(wn*64 + (lane & 7) + ((lane >> 4)*8))*80u
                         + (uint32_t)(((lane >> 3) & 1)*16);

    #pragma unroll
    for (int mt = 0; mt < 2; mt++)
        #pragma unroll
        for (int nt = 0; nt < 8; nt++)
            #pragma unroll
            for (int q = 0; q < 4; q++) acc[mt][nt][q] = 0.f;

    const float* pa = Ag + (size_t)lr*D_MODEL + lc;
    const float* pb = Bg + (size_t)lr*D_MODEL + lc;
    float va[16], vb[16];
    #pragma unroll
    for (int q = 0; q < 4; q++) {
        *(float4*)(va + 4*q) = *(const float4*)(pa + 4*q);
        *(float4*)(vb + 4*q) = *(const float4*)(pb + 4*q);
    }

    for (int c = 0; c < 32; c++) {
        char* st = sm + (c & 1)*STG_SZ;
        pack_store(st + lr*80 + lc*2,          st + AL_OFF + lr*80 + lc*2, va);
        pack_store(st + BH_OFF + lr*80 + lc*2, st + BL_OFF + lr*80 + lc*2, vb);
        __syncthreads();
        if (c < 31) {
            #pragma unroll
            for (int q = 0; q < 4; q++) {
                *(float4*)(va + 4*q) = *(const float4*)(pa + (c+1)*32 + 4*q);
                *(float4*)(vb + 4*q) = *(const float4*)(pb + (c+1)*32 + 4*q);
            }
        }
        uint32_t stg = sbase + (c & 1)*STG_SZ;
        #pragma unroll
        for (int ks = 0; ks < 2; ks++) {
            uint32_t ko = ks*32u;
            uint32_t aH[2][4], aL[2][4];
            ldsm4(aH[0], stg + a_off + ko);
            ldsm4(aH[1], stg + a_off + 1280u + ko);
            ldsm4(aL[0], stg + AL_OFF + a_off + ko);
            ldsm4(aL[1], stg + AL_OFF + a_off + 1280u + ko);
            uint32_t bH[4][4], bL[4][4];
            #pragma unroll
            for (int p = 0; p < 4; p++) {
                ldsm4(bH[p], stg + BH_OFF + b_off + p*1280u + ko);
                ldsm4(bL[p], stg + BL_OFF + b_off + p*1280u + ko);
            }
            #pragma unroll
            for (int mt = 0; mt < 2; mt++)
                #pragma unroll
                for (int nt = 0; nt < 8; nt++) {
                    uint32_t b0 = bH[nt>>1][(nt&1)*2], b1 = bH[nt>>1][(nt&1)*2+1];
                    uint32_t c0 = bL[nt>>1][(nt&1)*2], c1 = bL[nt>>1][(nt&1)*2+1];
                    mma16816(acc[mt][nt], aH[mt], b0, b1);
                    mma16816(acc[mt][nt], aL[mt], b0, b1);
                    mma16816(acc[mt][nt], aH[mt], c0, c1);
                }
        }
        __syncthreads();
    }
}

// =============== fused QKV GEMM + RoPE epilogue ===============
__global__ __launch_bounds__(256) void tc_qkv_kernel(
    const float* __restrict__ x,
    const float* __restrict__ Wq,
    const float* __restrict__ Wk,
    const float* __restrict__ Wv)
{
    extern __shared__ char sm[];
    const int tid = threadIdx.x;
    const int z = blockIdx.z;
    const float* __restrict__ W = (z == 0) ? Wq : ((z == 1) ? Wk : Wv);
    const int m0 = blockIdx.y * 128;
    const int n0 = blockIdx.x * 128;

    float acc[2][8][4];
    bf16_gemm_core(x + (size_t)m0*D_MODEL, W + (size_t)n0*D_MODEL, sm, tid, acc);

    const int lane = tid & 31, warp = tid >> 5;
    const int wm = warp & 3, wn = warp >> 2;
    float* outp = (z == 0) ? g_Q : ((z == 1) ? g_K : g_V);

    #pragma unroll
    for (int mt = 0; mt < 2; mt++) {
        #pragma unroll
        for (int rr = 0; rr < 2; rr++) {
            int m = m0 + wm*32 + mt*16 + (lane >> 2) + rr*8;
            int b = m >> 11, s = m & (SEQ-1);
            #pragma unroll
            for (int nt = 0; nt < 8; nt++) {
                int n = n0 + wn*64 + nt*8 + (lane & 3)*2;
                int h = n >> 6, d = n & 63;
                float x1 = acc[mt][nt][rr*2], x2 = acc[mt][nt][rr*2+1];
                float o1, o2;
                if (z < 2) {
                    float cv = g_cos[s*(DK/2) + (d >> 1)];
                    float sv = g_sin[s*(DK/2) + (d >> 1)];
                    o1 = cv*x1 - sv*x2;
                    o2 = sv*x1 + cv*x2;
                } else {
                    o1 = x1; o2 = x2;
                }
                *(float2*)(outp + ((size_t)(b*NHEADS + h)*SEQ + s)*DK + d) = make_float2(o1, o2);
            }
        }
    }
}

// =============== output projection ===============
__global__ __launch_bounds__(256) void tc_out_kernel(
    const float* __restrict__ Wo, float* __restrict__ out)
{
    extern __shared__ char sm[];
    const int tid = threadIdx.x;
    const int m0 = blockIdx.y * 128;
    const int n0 = blockIdx.x * 128;

    float acc[2][8][4];
    bf16_gemm_core(g_A + (size_t)m0*D_MODEL, Wo + (size_t)n0*D_MODEL, sm, tid, acc);

    const int lane = tid & 31, warp = tid >> 5;
    const int wm = warp & 3, wn = warp >> 2;

    #pragma unroll
    for (int mt = 0; mt < 2; mt++) {
        #pragma unroll
        for (int rr = 0; rr < 2; rr++) {
            int m = m0 + wm*32 + mt*16 + (lane >> 2) + rr*8;
            #pragma unroll
            for (int nt = 0; nt < 8; nt++) {
                int n = n0 + wn*64 + nt*8 + (lane & 3)*2;
                *(float2*)(out + (size_t)m*D_MODEL + n) =
                    make_float2(acc[mt][nt][rr*2], acc[mt][nt][rr*2+1]);
            }
        }
    }
}

// ---------------- flash attention (causal, fp32, scalar — round-2 proven) ----------------
__global__ __launch_bounds__(256,2) void flash_kernel()
{
    extern __shared__ float smf[];
    float (*Qs)[132] = (float(*)[132])(smf);
    float (*Ks)[68]  = (float(*)[68]) (smf + 64*132);
    float (*Vs)[68]  = (float(*)[68]) (smf + 64*132 + 64*68);
    float (*Ps)[132] = (float(*)[132])(smf + 64*132 + 2*64*68);

    const int tid = threadIdx.x;
    const int tx = tid & 15, ty = tid >> 4;
    const int qt = gridDim.x - 1 - blockIdx.x;
    const int bh = blockIdx.y;
    const int b  = bh >> 4, h = bh & 15;

    const float* __restrict__ Qg = g_Q + (size_t)bh*SEQ*DK;
    const float* __restrict__ Kg = g_K + (size_t)bh*SEQ*DK;
    const float* __restrict__ Vg = g_V + (size_t)bh*SEQ*DK;

    #pragma unroll
    for (int it = 0; it < 8; it++) {
        int idx = tid + it*256;
        int rq = idx >> 4, c4 = (idx & 15) << 2;
        float4 v = *(const float4*)(Qg + (size_t)(qt*128 + rq)*DK + c4);
        Qs[c4+0][rq]=v.x; Qs[c4+1][rq]=v.y; Qs[c4+2][rq]=v.z; Qs[c4+3][rq]=v.w;
    }

    float o[8][4] = {};
    float m_i[8], l_i[8];
    #pragma unroll
    for (int i = 0; i < 8; i++) { m_i[i] = -1e30f; l_i[i] = 0.f; }

    const float SC = 0.18033688011112042f;  // log2(e)/sqrt(64)
    const int ktmax = 2*qt + 1;

    for (int kt = 0; kt <= ktmax; kt++) {
        __syncthreads();
        #pragma unroll
        for (int it = 0; it < 4; it++) {
            int idx = tid + it*256;
            int rk = idx >> 4, c4 = (idx & 15) << 2;
            float4 kv = *(const float4*)(Kg + (size_t)(kt*64 + rk)*DK + c4);
            Ks[c4+0][rk]=kv.x; Ks[c4+1][rk]=kv.y; Ks[c4+2][rk]=kv.z; Ks[c4+3][rk]=kv.w;
            float4 vv = *(const float4*)(Vg + (size_t)(kt*64 + rk)*DK + c4);
            *(float4*)&Vs[rk][c4] = vv;
        }
        __syncthreads();

        float s_[8][4] = {};
        #pragma unroll 8
        for (int d = 0; d < 64; d++) {
            float rq[8], rk[4];
            *(float4*)(rq)   = *(const float4*)&Qs[d][ty*8];
            *(float4*)(rq+4) = *(const float4*)&Qs[d][ty*8+4];
            *(float4*)(rk)   = *(const float4*)&Ks[d][tx*4];
            #pragma unroll
            for (int i = 0; i < 8; i++)
                #pragma unroll
                for (int j = 0; j < 4; j++)
                    s_[i][j] = fmaf(rq[i], rk[j], s_[i][j]);
        }

        if (kt >= 2*qt) {
            #pragma unroll
            for (int i = 0; i < 8; i++) {
                int qi = qt*128 + ty*8 + i;
                #pragma unroll
                for (int j = 0; j < 4; j++) {
                    int kj = kt*64 + tx*4 + j;
                    s_[i][j] = (kj <= qi) ? s_[i][j]*SC : -1e30f;
                }
            }
        } else {
            #pragma unroll
            for (int i = 0; i < 8; i++)
                #pragma unroll
                for (int j = 0; j < 4; j++)
                    s_[i][j] *= SC;
        }

        #pragma unroll
        for (int i = 0; i < 8; i++) {
            float mx = fmaxf(fmaxf(s_[i][0],s_[i][1]), fmaxf(s_[i][2],s_[i][3]));
            #pragma unroll
            for (int off = 8; off >= 1; off >>= 1)
                mx = fmaxf(mx, __shfl_xor_sync(0xffffffffu, mx, off, 16));
            float mnew = fmaxf(m_i[i], mx);
            float p[4], rs = 0.f;
            #pragma unroll
            for (int j = 0; j < 4; j++) { p[j] = exp2f_fast(s_[i][j] - mnew); rs += p[j]; }
            #pragma unroll
            for (int off = 8; off >= 1; off >>= 1)
                rs += __shfl_xor_sync(0xffffffffu, rs, off, 16);
            float corr = exp2f_fast(m_i[i] - mnew);
            l_i[i] = l_i[i]*corr + rs;
            m_i[i] = mnew;
            #pragma unroll
            for (int j = 0; j < 4; j++) {
                o[i][j] *= corr;
                Ps[tx*4+j][ty*8+i] = p[j];
            }
        }
        __syncthreads();

        #pragma unroll 8
        for (int k = 0; k < 64; k++) {
            float rp[8], rv[4];
            *(float4*)(rp)   = *(const float4*)&Ps[k][ty*8];
            *(float4*)(rp+4) = *(const float4*)&Ps[k][ty*8+4];
            *(float4*)(rv)   = *(const float4*)&Vs[k][tx*4];
            #pragma unroll
            for (int i = 0; i < 8; i++)
                #pragma unroll
                for (int j = 0; j < 4; j++)
                    o[i][j] = fmaf(rp[i], rv[j], o[i][j]);
        }
    }

    #pragma unroll
    for (int i = 0; i < 8; i++) {
        float inv = 1.0f / l_i[i];
        int s_idx = qt*128 + ty*8 + i;
        float4 val = make_float4(o[i][0]*inv, o[i][1]*inv, o[i][2]*inv, o[i][3]*inv);
        *(float4*)(g_A + ((size_t)b*SEQ + s_idx)*D_MODEL + h*DK + tx*4) = val;
    }
}

// ---------------- launch ----------------
extern "C" void kernel_launch(void* const* d_in, const int* in_sizes, int n_in,
                              void* d_out, int out_size)
{
    const float* x  = (const float*)d_in[0];
    const float* Wq = (const float*)d_in[1];
    const float* Wk = (const float*)d_in[2];
    const float* Wv = (const float*)d_in[3];
    const float* Wo = (const float*)d_in[4];
    float* out = (float*)d_out;

    const int gemm_smem  = 2*STG_SZ;                            // 81920 B
    const int flash_smem = (64*132 + 2*64*68 + 64*132) * 4;     // 102400 B
    cudaFuncSetAttribute(tc_qkv_kernel, cudaFuncAttributeMaxDynamicSharedMemorySize, gemm_smem);
    cudaFuncSetAttribute(tc_out_kernel, cudaFuncAttributeMaxDynamicSharedMemorySize, gemm_smem);
    cudaFuncSetAttribute(flash_kernel,  cudaFuncAttributeMaxDynamicSharedMemorySize, flash_smem);

    rope_table_kernel<<<(SEQ*(DK/2) + 255)/256, 256>>>();

    dim3 g1(D_MODEL/128, MTOT/128, 3);
    tc_qkv_kernel<<<g1, 256, gemm_smem>>>(x, Wq, Wk, Wv);

    dim3 g2(SEQ/128, BATCH*NHEADS);
    flash_kernel<<<g2, 256, flash_smem>>>();

    dim3 g3(D_MODEL/128, MTOT/128);
    tc_out_kernel<<<g3, 256, gemm_smem>>>(Wo, out);
}

// round 6
// speedup vs baseline: 4.6081x; 1.5745x over previous
#include <cuda_runtime.h>
#include <cuda_bf16.h>
#include <cstdint>
#include <math.h>

#define D_MODEL 1024
#define NHEADS  16
#define DK      64
#define SEQ     2048
#define BATCH   2
#define MTOT    (BATCH*SEQ)
#define NBH     (BATCH*NHEADS)

// ---- device scratch (no cudaMalloc allowed) ----
__device__ __nv_bfloat16 g_Qh[(size_t)NBH*SEQ*DK];
__device__ __nv_bfloat16 g_Ql[(size_t)NBH*SEQ*DK];
__device__ __nv_bfloat16 g_Kh[(size_t)NBH*SEQ*DK];
__device__ __nv_bfloat16 g_Kl[(size_t)NBH*SEQ*DK];
__device__ __nv_bfloat16 g_Vth[(size_t)NBH*DK*SEQ];   // transposed: [bh][d][s]
__device__ __nv_bfloat16 g_Vtl[(size_t)NBH*DK*SEQ];
__device__ float g_A[(size_t)MTOT*D_MODEL];
__device__ float g_cos[SEQ*(DK/2)];
__device__ float g_sin[SEQ*(DK/2)];

// =============== helpers ===============
__device__ __forceinline__ uint32_t smem_u32(const void* p) {
    uint32_t a;
    asm("{ .reg .u64 t; cvta.to.shared.u64 t, %1; cvt.u32.u64 %0, t; }" : "=r"(a) : "l"(p));
    return a;
}
__device__ __forceinline__ void ldsm4(uint32_t* r, uint32_t a) {
    asm volatile("ldmatrix.sync.aligned.m8n8.x4.shared.b16 {%0,%1,%2,%3}, [%4];"
        : "=r"(r[0]), "=r"(r[1]), "=r"(r[2]), "=r"(r[3]) : "r"(a));
}
__device__ __forceinline__ void mma16816(float* d, const uint32_t* a, uint32_t b0, uint32_t b1) {
    asm volatile("mma.sync.aligned.m16n8k16.row.col.f32.bf16.bf16.f32 "
        "{%0,%1,%2,%3},{%4,%5,%6,%7},{%8,%9},{%0,%1,%2,%3};"
        : "+f"(d[0]), "+f"(d[1]), "+f"(d[2]), "+f"(d[3])
        : "r"(a[0]), "r"(a[1]), "r"(a[2]), "r"(a[3]), "r"(b0), "r"(b1));
}
__device__ __forceinline__ uint32_t cvt2(float a, float b) {
    __nv_bfloat162 t = __floats2bfloat162_rn(a, b);
    return *(uint32_t*)&t;
}
__device__ __forceinline__ uint32_t cvt2res(float a, float b, uint32_t h) {
    __nv_bfloat162 th = *(__nv_bfloat162*)&h;
    return cvt2(a - __low2float(th), b - __high2float(th));
}
#define CP16(d, s) asm volatile("cp.async.cg.shared.global [%0], [%1], 16;" :: "r"(d), "l"(s))
#define CPC()      asm volatile("cp.async.commit_group;" ::: "memory")
#define CPW(n)     asm volatile("cp.async.wait_group %0;" :: "n"(n) : "memory")

// ---------------- RoPE table ----------------
__global__ void rope_table_kernel() {
    int i = blockIdx.x*blockDim.x + threadIdx.x;
    if (i >= SEQ*(DK/2)) return;
    int s = i / (DK/2);
    int j = i % (DK/2);
    double freq = pow(10000.0, -(double)(2*j)/(double)DK);
    double ang  = (double)s * freq;
    g_cos[i] = (float)cos(ang);
    g_sin[i] = (float)sin(ang);
}

__device__ __forceinline__ float exp2f_fast(float x) {
    x = fmaxf(x, -125.0f);
    float t = x + 12582912.0f;
    float f = x - (t - 12582912.0f);
    int   e = __float_as_int(t) << 23;
    float p = 1.5402387e-4f;
    p = fmaf(p, f, 1.3333558e-3f);
    p = fmaf(p, f, 9.6181291e-3f);
    p = fmaf(p, f, 5.5504109e-2f);
    p = fmaf(p, f, 2.4022651e-1f);
    p = fmaf(p, f, 6.9314718e-1f);
    p = fmaf(p, f, 1.0f);
    return __int_as_float(__float_as_int(p) + e);
}

// =============== bf16 3-split GEMM core (proven in R5) ===============
#define STG_SZ 40960u
#define AL_OFF 10240u
#define BH_OFF 20480u
#define BL_OFF 30720u

__device__ __forceinline__ void pack_store(char* dst_h, char* dst_l, const float* f) {
    uint32_t H[8], L[8];
    #pragma unroll
    for (int i = 0; i < 8; i++) {
        float f0 = f[2*i], f1 = f[2*i+1];
        __nv_bfloat162 h2 = __floats2bfloat162_rn(f0, f1);
        float r0 = f0 - __low2float(h2);
        float r1 = f1 - __high2float(h2);
        __nv_bfloat162 l2 = __floats2bfloat162_rn(r0, r1);
        H[i] = *(uint32_t*)&h2;
        L[i] = *(uint32_t*)&l2;
    }
    *(uint4*)(dst_h)      = make_uint4(H[0], H[1], H[2], H[3]);
    *(uint4*)(dst_h + 16) = make_uint4(H[4], H[5], H[6], H[7]);
    *(uint4*)(dst_l)      = make_uint4(L[0], L[1], L[2], L[3]);
    *(uint4*)(dst_l + 16) = make_uint4(L[4], L[5], L[6], L[7]);
}

__device__ __forceinline__ void bf16_gemm_core(
    const float* __restrict__ Ag, const float* __restrict__ Bg,
    char* sm, int tid, float acc[2][8][4])
{
    const int lane = tid & 31, warp = tid >> 5;
    const int wm = warp & 3, wn = warp >> 2;
    const int lr = tid >> 1;
    const int lc = (tid & 1) * 16;
    const uint32_t sbase = smem_u32(sm);

    const uint32_t a_off = (uint32_t)(wm*32 + (lane & 15))*80u + (uint32_t)((lane >> 4)*16);
    const uint32_t b_off = (uint32_t)(wn*64 + (lane & 7) + ((lane >> 4)*8))*80u
                         + (uint32_t)(((lane >> 3) & 1)*16);

    #pragma unroll
    for (int mt = 0; mt < 2; mt++)
        #pragma unroll
        for (int nt = 0; nt < 8; nt++)
            #pragma unroll
            for (int q = 0; q < 4; q++) acc[mt][nt][q] = 0.f;

    const float* pa = Ag + (size_t)lr*D_MODEL + lc;
    const float* pb = Bg + (size_t)lr*D_MODEL + lc;
    float va[16], vb[16];
    #pragma unroll
    for (int q = 0; q < 4; q++) {
        *(float4*)(va + 4*q) = *(const float4*)(pa + 4*q);
        *(float4*)(vb + 4*q) = *(const float4*)(pb + 4*q);
    }

    for (int c = 0; c < 32; c++) {
        char* st = sm + (c & 1)*STG_SZ;
        pack_store(st + lr*80 + lc*2,          st + AL_OFF + lr*80 + lc*2, va);
        pack_store(st + BH_OFF + lr*80 + lc*2, st + BL_OFF + lr*80 + lc*2, vb);
        __syncthreads();
        if (c < 31) {
            #pragma unroll
            for (int q = 0; q < 4; q++) {
                *(float4*)(va + 4*q) = *(const float4*)(pa + (c+1)*32 + 4*q);
                *(float4*)(vb + 4*q) = *(const float4*)(pb + (c+1)*32 + 4*q);
            }
        }
        uint32_t stg = sbase + (c & 1)*STG_SZ;
        #pragma unroll
        for (int ks = 0; ks < 2; ks++) {
            uint32_t ko = ks*32u;
            uint32_t aH[2][4], aL[2][4];
            ldsm4(aH[0], stg + a_off + ko);
            ldsm4(aH[1], stg + a_off + 1280u + ko);
            ldsm4(aL[0], stg + AL_OFF + a_off + ko);
            ldsm4(aL[1], stg + AL_OFF + a_off + 1280u + ko);
            uint32_t bH[4][4], bL[4][4];
            #pragma unroll
            for (int p = 0; p < 4; p++) {
                ldsm4(bH[p], stg + BH_OFF + b_off + p*1280u + ko);
                ldsm4(bL[p], stg + BL_OFF + b_off + p*1280u + ko);
            }
            #pragma unroll
            for (int mt = 0; mt < 2; mt++)
                #pragma unroll
                for (int nt = 0; nt < 8; nt++) {
                    uint32_t b0 = bH[nt>>1][(nt&1)*2], b1 = bH[nt>>1][(nt&1)*2+1];
                    uint32_t c0 = bL[nt>>1][(nt&1)*2], c1 = bL[nt>>1][(nt&1)*2+1];
                    mma16816(acc[mt][nt], aH[mt], b0, b1);
                    mma16816(acc[mt][nt], aL[mt], b0, b1);
                    mma16816(acc[mt][nt], aH[mt], c0, c1);
                }
        }
        __syncthreads();
    }
}

// =============== fused QKV GEMM + RoPE + bf16-split store ===============
__global__ __launch_bounds__(256) void tc_qkv_kernel(
    const float* __restrict__ x,
    const float* __restrict__ Wq,
    const float* __restrict__ Wk,
    const float* __restrict__ Wv)
{
    extern __shared__ char sm[];
    const int tid = threadIdx.x;
    const int z = blockIdx.z;
    const float* __restrict__ W = (z == 0) ? Wq : ((z == 1) ? Wk : Wv);
    const int m0 = blockIdx.y * 128;
    const int n0 = blockIdx.x * 128;

    float acc[2][8][4];
    bf16_gemm_core(x + (size_t)m0*D_MODEL, W + (size_t)n0*D_MODEL, sm, tid, acc);

    const int lane = tid & 31, warp = tid >> 5;
    const int wm = warp & 3, wn = warp >> 2;

    #pragma unroll
    for (int mt = 0; mt < 2; mt++) {
        #pragma unroll
        for (int rr = 0; rr < 2; rr++) {
            int m = m0 + wm*32 + mt*16 + (lane >> 2) + rr*8;
            int b = m >> 11, s = m & (SEQ-1);
            int bh = b*NHEADS;
            #pragma unroll
            for (int nt = 0; nt < 8; nt++) {
                int n = n0 + wn*64 + nt*8 + (lane & 3)*2;
                int h = n >> 6, d = n & 63;
                float x1 = acc[mt][nt][rr*2], x2 = acc[mt][nt][rr*2+1];
                if (z < 2) {
                    float cv = g_cos[s*(DK/2) + (d >> 1)];
                    float sv = g_sin[s*(DK/2) + (d >> 1)];
                    float o1 = cv*x1 - sv*x2;
                    float o2 = sv*x1 + cv*x2;
                    uint32_t hv = cvt2(o1, o2);
                    uint32_t lv = cvt2res(o1, o2, hv);
                    size_t base = ((size_t)(bh + h)*SEQ + s)*DK + d;
                    if (z == 0) {
                        *(uint32_t*)(g_Qh + base) = hv;
                        *(uint32_t*)(g_Ql + base) = lv;
                    } else {
                        *(uint32_t*)(g_Kh + base) = hv;
                        *(uint32_t*)(g_Kl + base) = lv;
                    }
                } else {
                    size_t tb = ((size_t)(bh + h)*DK + d)*SEQ + s;
                    __nv_bfloat16 h1 = __float2bfloat16_rn(x1);
                    __nv_bfloat16 h2 = __float2bfloat16_rn(x2);
                    g_Vth[tb]       = h1;
                    g_Vth[tb + SEQ] = h2;
                    g_Vtl[tb]       = __float2bfloat16_rn(x1 - __bfloat162float(h1));
                    g_Vtl[tb + SEQ] = __float2bfloat16_rn(x2 - __bfloat162float(h2));
                }
            }
        }
    }
}

// =============== output projection ===============
__global__ __launch_bounds__(256) void tc_out_kernel(
    const float* __restrict__ Wo, float* __restrict__ out)
{
    extern __shared__ char sm[];
    const int tid = threadIdx.x;
    const int m0 = blockIdx.y * 128;
    const int n0 = blockIdx.x * 128;

    float acc[2][8][4];
    bf16_gemm_core(g_A + (size_t)m0*D_MODEL, Wo + (size_t)n0*D_MODEL, sm, tid, acc);

    const int lane = tid & 31, warp = tid >> 5;
    const int wm = warp & 3, wn = warp >> 2;

    #pragma unroll
    for (int mt = 0; mt < 2; mt++) {
        #pragma unroll
        for (int rr = 0; rr < 2; rr++) {
            int m = m0 + wm*32 + mt*16 + (lane >> 2) + rr*8;
            #pragma unroll
            for (int nt = 0; nt < 8; nt++) {
                int n = n0 + wn*64 + nt*8 + (lane & 3)*2;
                *(float2*)(out + (size_t)m*D_MODEL + n) =
                    make_float2(acc[mt][nt][rr*2], acc[mt][nt][rr*2+1]);
            }
        }
    }
}

// =============== flash attention (HMMA bf16 3-split) ===============
// BM=128, BN=64. 8 warps, each owns m16. Q frags in regs; K/Vt double-buffered cp.async.
// Stage: Kh@0 Kl@9216 Vth@18432 Vtl@27648 (rows 144B stride); Q at 73728.
#define FSTG 36864u

__global__ __launch_bounds__(256,1) void flash_kernel()
{
    extern __shared__ char sm[];
    const uint32_t sb = smem_u32(sm);
    const int tid = threadIdx.x;
    const int lane = tid & 31, w = tid >> 5;
    const int qt = gridDim.x - 1 - (int)blockIdx.x;
    const int bh = blockIdx.y;
    const int b = bh >> 4, h = bh & 15;

    const __nv_bfloat16* Qhg = g_Qh + (size_t)bh*SEQ*DK + (size_t)qt*128*DK;
    const __nv_bfloat16* Qlg = g_Ql + (size_t)bh*SEQ*DK + (size_t)qt*128*DK;
    const __nv_bfloat16* Khg = g_Kh + (size_t)bh*SEQ*DK;
    const __nv_bfloat16* Klg = g_Kl + (size_t)bh*SEQ*DK;
    const __nv_bfloat16* Vhg = g_Vth + (size_t)bh*DK*SEQ;
    const __nv_bfloat16* Vlg = g_Vtl + (size_t)bh*DK*SEQ;

    const uint32_t QH = sb + 2*FSTG, QL = QH + 18432u;

    // Q load (group 0)
    #pragma unroll
    for (int i = 0; i < 4; i++) {
        int idx = tid + i*256;
        int r = idx >> 3, c = idx & 7;
        CP16(QH + r*144 + c*16, Qhg + r*64 + c*8);
        CP16(QL + r*144 + c*16, Qlg + r*64 + c*8);
    }
    CPC();
    // KV stage 0 (group 1)
    #pragma unroll
    for (int i = 0; i < 2; i++) {
        int idx = tid + i*256;
        int r = idx >> 3, c = idx & 7;
        CP16(sb + r*144 + c*16,           Khg + r*64 + c*8);
        CP16(sb + 9216u + r*144 + c*16,   Klg + r*64 + c*8);
        CP16(sb + 18432u + r*144 + c*16,  Vhg + (size_t)r*SEQ + c*8);
        CP16(sb + 27648u + r*144 + c*16,  Vlg + (size_t)r*SEQ + c*8);
    }
    CPC();
    CPW(1);            // Q done; KV0 in flight
    __syncthreads();

    // Q fragments (register-resident for entire kv loop)
    uint32_t qfh[4][4], qfl[4][4];
    const uint32_t a_off = (uint32_t)((w*16 + (lane & 15))*144) + (uint32_t)((lane >> 4)*16);
    #pragma unroll
    for (int kc = 0; kc < 4; kc++) {
        ldsm4(qfh[kc], QH + a_off + kc*32);
        ldsm4(qfl[kc], QL + a_off + kc*32);
    }

    const uint32_t b_off = (uint32_t)(((lane & 7) + ((lane >> 4)*8))*144)
                         + (uint32_t)(((lane >> 3) & 1)*16);

    float o[8][4];
    #pragma unroll
    for (int dt = 0; dt < 8; dt++)
        #pragma unroll
        for (int q = 0; q < 4; q++) o[dt][q] = 0.f;
    float m0 = -1e30f, m1 = -1e30f, l0 = 0.f, l1 = 0.f;
    const float SC = 0.18033688011112042f;   // log2(e)/sqrt(64)
    const int ktmax = 2*qt + 1;

    for (int kt = 0; kt <= ktmax; kt++) {
        if (kt < ktmax) {
            uint32_t st = sb + ((kt+1) & 1)*FSTG;
            const __nv_bfloat16* kh = Khg + (size_t)(kt+1)*64*DK;
            const __nv_bfloat16* kl = Klg + (size_t)(kt+1)*64*DK;
            #pragma unroll
            for (int i = 0; i < 2; i++) {
                int idx = tid + i*256;
                int r = idx >> 3, c = idx & 7;
                CP16(st + r*144 + c*16,          kh + r*64 + c*8);
                CP16(st + 9216u + r*144 + c*16,  kl + r*64 + c*8);
                CP16(st + 18432u + r*144 + c*16, Vhg + (size_t)r*SEQ + (kt+1)*64 + c*8);
                CP16(st + 27648u + r*144 + c*16, Vlg + (size_t)r*SEQ + (kt+1)*64 + c*8);
            }
            CPC();
            CPW(1);
        } else {
            CPW(0);
        }
        __syncthreads();

        const uint32_t st = sb + (kt & 1)*FSTG;

        // ---- QK^T ----
        float acc[8][4];
        #pragma unroll
        for (int nt = 0; nt < 8; nt++)
            #pragma unroll
            for (int q = 0; q < 4; q++) acc[nt][q] = 0.f;

        #pragma unroll
        for (int kc = 0; kc < 4; kc++) {
            uint32_t kbh[4][4], kbl[4][4];
            #pragma unroll
            for (int g = 0; g < 4; g++) {
                ldsm4(kbh[g], st + b_off + g*2304u + kc*32);
                ldsm4(kbl[g], st + 9216u + b_off + g*2304u + kc*32);
            }
            #pragma unroll
            for (int nt = 0; nt < 8; nt++) {
                uint32_t b0 = kbh[nt>>1][(nt&1)*2], b1 = kbh[nt>>1][(nt&1)*2+1];
                uint32_t c0 = kbl[nt>>1][(nt&1)*2], c1 = kbl[nt>>1][(nt&1)*2+1];
                mma16816(acc[nt], qfh[kc], b0, b1);
                mma16816(acc[nt], qfl[kc], b0, b1);
                mma16816(acc[nt], qfh[kc], c0, c1);
            }
        }

        // ---- mask + scale ----
        if (kt >= 2*qt) {
            #pragma unroll
            for (int nt = 0; nt < 8; nt++)
                #pragma unroll
                for (int j = 0; j < 4; j++) {
                    int kj = kt*64 + nt*8 + ((lane & 3) << 1) + (j & 1);
                    int qi = qt*128 + w*16 + (lane >> 2) + ((j >> 1) << 3);
                    acc[nt][j] = (kj <= qi) ? acc[nt][j]*SC : -1e30f;
                }
        } else {
            #pragma unroll
            for (int nt = 0; nt < 8; nt++)
                #pragma unroll
                for (int j = 0; j < 4; j++) acc[nt][j] *= SC;
        }

        // ---- online softmax (rows r and r+8) ----
        float mx0 = -1e30f, mx1 = -1e30f;
        #pragma unroll
        for (int nt = 0; nt < 8; nt++) {
            mx0 = fmaxf(mx0, fmaxf(acc[nt][0], acc[nt][1]));
            mx1 = fmaxf(mx1, fmaxf(acc[nt][2], acc[nt][3]));
        }
        mx0 = fmaxf(mx0, __shfl_xor_sync(0xffffffffu, mx0, 1));
        mx0 = fmaxf(mx0, __shfl_xor_sync(0xffffffffu, mx0, 2));
        mx1 = fmaxf(mx1, __shfl_xor_sync(0xffffffffu, mx1, 1));
        mx1 = fmaxf(mx1, __shfl_xor_sync(0xffffffffu, mx1, 2));
        float mn0 = fmaxf(m0, mx0), mn1 = fmaxf(m1, mx1);
        float rs0 = 0.f, rs1 = 0.f;
        #pragma unroll
        for (int nt = 0; nt < 8; nt++) {
            acc[nt][0] = exp2f_fast(acc[nt][0] - mn0);
            acc[nt][1] = exp2f_fast(acc[nt][1] - mn0);
            acc[nt][2] = exp2f_fast(acc[nt][2] - mn1);
            acc[nt][3] = exp2f_fast(acc[nt][3] - mn1);
            rs0 += acc[nt][0] + acc[nt][1];
            rs1 += acc[nt][2] + acc[nt][3];
        }
        rs0 += __shfl_xor_sync(0xffffffffu, rs0, 1);
        rs0 += __shfl_xor_sync(0xffffffffu, rs0, 2);
        rs1 += __shfl_xor_sync(0xffffffffu, rs1, 1);
        rs1 += __shfl_xor_sync(0xffffffffu, rs1, 2);
        float corr0 = exp2f_fast(m0 - mn0);
        float corr1 = exp2f_fast(m1 - mn1);
        l0 = l0*corr0 + rs0;  m0 = mn0;
        l1 = l1*corr1 + rs1;  m1 = mn1;
        #pragma unroll
        for (int dt = 0; dt < 8; dt++) {
            o[dt][0] *= corr0; o[dt][1] *= corr0;
            o[dt][2] *= corr1; o[dt][3] *= corr1;
        }

        // ---- PV: P fragments from registers (split Ph+Pl), V^T from smem ----
        #pragma unroll
        for (int kc = 0; kc < 4; kc++) {
            uint32_t pah[4], pal[4];
            pah[0] = cvt2(acc[2*kc][0],   acc[2*kc][1]);   pal[0] = cvt2res(acc[2*kc][0],   acc[2*kc][1],   pah[0]);
            pah[1] = cvt2(acc[2*kc][2],   acc[2*kc][3]);   pal[1] = cvt2res(acc[2*kc][2],   acc[2*kc][3],   pah[1]);
            pah[2] = cvt2(acc[2*kc+1][0], acc[2*kc+1][1]); pal[2] = cvt2res(acc[2*kc+1][0], acc[2*kc+1][1], pah[2]);
            pah[3] = cvt2(acc[2*kc+1][2], acc[2*kc+1][3]); pal[3] = cvt2res(acc[2*kc+1][2], acc[2*kc+1][3], pah[3]);
            uint32_t vbh[4][4], vbl[4][4];
            #pragma unroll
            for (int g = 0; g < 4; g++) {
                ldsm4(vbh[g], st + 18432u + b_off + g*2304u + kc*32);
                ldsm4(vbl[g], st + 27648u + b_off + g*2304u + kc*32);
            }
            #pragma unroll
            for (int dt = 0; dt < 8; dt++) {
                uint32_t b0 = vbh[dt>>1][(dt&1)*2], b1 = vbh[dt>>1][(dt&1)*2+1];
                uint32_t c0 = vbl[dt>>1][(dt&1)*2], c1 = vbl[dt>>1][(dt&1)*2+1];
                mma16816(o[dt], pah, b0, b1);
                mma16816(o[dt], pal, b0, b1);
                mma16816(o[dt], pah, c0, c1);
            }
        }
        __syncthreads();
    }

    // ---- epilogue: normalize, write fp32 g_A [B,S,D_MODEL] ----
    float inv0 = 1.0f / l0, inv1 = 1.0f / l1;
    int r0 = qt*128 + w*16 + (lane >> 2);
    #pragma unroll
    for (int dt = 0; dt < 8; dt++) {
        int d = dt*8 + (lane & 3)*2;
        *(float2*)(g_A + ((size_t)b*SEQ + r0)*D_MODEL + h*64 + d) =
            make_float2(o[dt][0]*inv0, o[dt][1]*inv0);
        *(float2*)(g_A + ((size_t)b*SEQ + r0 + 8)*D_MODEL + h*64 + d) =
            make_float2(o[dt][2]*inv1, o[dt][3]*inv1);
    }
}

// ---------------- launch ----------------
extern "C" void kernel_launch(void* const* d_in, const int* in_sizes, int n_in,
                              void* d_out, int out_size)
{
    const float* x  = (const float*)d_in[0];
    const float* Wq = (const float*)d_in[1];
    const float* Wk = (const float*)d_in[2];
    const float* Wv = (const float*)d_in[3];
    const float* Wo = (const float*)d_in[4];
    float* out = (float*)d_out;

    const int gemm_smem  = 2*STG_SZ;                 // 81920 B
    const int flash_smem = 2*FSTG + 2*18432;         // 110592 B
    cudaFuncSetAttribute(tc_qkv_kernel, cudaFuncAttributeMaxDynamicSharedMemorySize, gemm_smem);
    cudaFuncSetAttribute(tc_out_kernel, cudaFuncAttributeMaxDynamicSharedMemorySize, gemm_smem);
    cudaFuncSetAttribute(flash_kernel,  cudaFuncAttributeMaxDynamicSharedMemorySize, flash_smem);

    rope_table_kernel<<<(SEQ*(DK/2) + 255)/256, 256>>>();

    dim3 g1(D_MODEL/128, MTOT/128, 3);
    tc_qkv_kernel<<<g1, 256, gemm_smem>>>(x, Wq, Wk, Wv);

    dim3 g2(SEQ/128, NBH);
    flash_kernel<<<g2, 256, flash_smem>>>();

    dim3 g3(D_MODEL/128, MTOT/128);
    tc_out_kernel<<<g3, 256, gemm_smem>>>(Wo, out);
}

// round 7
// speedup vs baseline: 5.6855x; 1.2338x over previous
#include <cuda_runtime.h>
#include <cuda_bf16.h>
#include <cstdint>
#include <math.h>

#define D_MODEL 1024
#define NHEADS  16
#define DK      64
#define SEQ     2048
#define BATCH   2
#define MTOT    (BATCH*SEQ)
#define NBH     (BATCH*NHEADS)

// ---- device scratch (no cudaMalloc allowed) ----
__device__ __nv_bfloat16 g_xh[(size_t)MTOT*D_MODEL];
__device__ __nv_bfloat16 g_xl[(size_t)MTOT*D_MODEL];
__device__ __nv_bfloat16 g_Wh[4][(size_t)D_MODEL*D_MODEL];   // q,k,v,o
__device__ __nv_bfloat16 g_Wl[4][(size_t)D_MODEL*D_MODEL];
__device__ __nv_bfloat16 g_Qh[(size_t)NBH*SEQ*DK];
__device__ __nv_bfloat16 g_Ql[(size_t)NBH*SEQ*DK];
__device__ __nv_bfloat16 g_Kh[(size_t)NBH*SEQ*DK];
__device__ __nv_bfloat16 g_Kl[(size_t)NBH*SEQ*DK];
__device__ __nv_bfloat16 g_Vth[(size_t)NBH*DK*SEQ];   // transposed: [bh][d][s]
__device__ __nv_bfloat16 g_Vtl[(size_t)NBH*DK*SEQ];
__device__ __nv_bfloat16 g_Ah[(size_t)MTOT*D_MODEL];  // attention out, split
__device__ __nv_bfloat16 g_Al[(size_t)MTOT*D_MODEL];
__device__ float g_cos[SEQ*(DK/2)];
__device__ float g_sin[SEQ*(DK/2)];

// =============== helpers ===============
__device__ __forceinline__ uint32_t smem_u32(const void* p) {
    uint32_t a;
    asm("{ .reg .u64 t; cvta.to.shared.u64 t, %1; cvt.u32.u64 %0, t; }" : "=r"(a) : "l"(p));
    return a;
}
__device__ __forceinline__ void ldsm4(uint32_t* r, uint32_t a) {
    asm volatile("ldmatrix.sync.aligned.m8n8.x4.shared.b16 {%0,%1,%2,%3}, [%4];"
        : "=r"(r[0]), "=r"(r[1]), "=r"(r[2]), "=r"(r[3]) : "r"(a));
}
__device__ __forceinline__ void mma16816(float* d, const uint32_t* a, uint32_t b0, uint32_t b1) {
    asm volatile("mma.sync.aligned.m16n8k16.row.col.f32.bf16.bf16.f32 "
        "{%0,%1,%2,%3},{%4,%5,%6,%7},{%8,%9},{%0,%1,%2,%3};"
        : "+f"(d[0]), "+f"(d[1]), "+f"(d[2]), "+f"(d[3])
        : "r"(a[0]), "r"(a[1]), "r"(a[2]), "r"(a[3]), "r"(b0), "r"(b1));
}
__device__ __forceinline__ uint32_t cvt2(float a, float b) {
    __nv_bfloat162 t = __floats2bfloat162_rn(a, b);
    return *(uint32_t*)&t;
}
__device__ __forceinline__ uint32_t cvt2res(float a, float b, uint32_t h) {
    __nv_bfloat162 th = *(__nv_bfloat162*)&h;
    return cvt2(a - __low2float(th), b - __high2float(th));
}
#define CP16(d, s) asm volatile("cp.async.cg.shared.global [%0], [%1], 16;" :: "r"(d), "l"(s))
#define CPC()      asm volatile("cp.async.commit_group;" ::: "memory")
#define CPW(n)     asm volatile("cp.async.wait_group %0;" :: "n"(n) : "memory")

// ---------------- RoPE table ----------------
__global__ void rope_table_kernel() {
    int i = blockIdx.x*blockDim.x + threadIdx.x;
    if (i >= SEQ*(DK/2)) return;
    int s = i / (DK/2);
    int j = i % (DK/2);
    double freq = pow(10000.0, -(double)(2*j)/(double)DK);
    double ang  = (double)s * freq;
    g_cos[i] = (float)cos(ang);
    g_sin[i] = (float)sin(ang);
}

__device__ __forceinline__ float exp2f_fast(float x) {
    x = fmaxf(x, -125.0f);
    float t = x + 12582912.0f;
    float f = x - (t - 12582912.0f);
    int   e = __float_as_int(t) << 23;
    float p = 1.5402387e-4f;
    p = fmaf(p, f, 1.3333558e-3f);
    p = fmaf(p, f, 9.6181291e-3f);
    p = fmaf(p, f, 5.5504109e-2f);
    p = fmaf(p, f, 2.4022651e-1f);
    p = fmaf(p, f, 6.9314718e-1f);
    p = fmaf(p, f, 1.0f);
    return __int_as_float(__float_as_int(p) + e);
}

// ---------------- fp32 -> bf16 h/l split (pre-pass) ----------------
__global__ void split_kernel(const float* __restrict__ s, int sel, int n) {
    __nv_bfloat16 *h, *l;
    switch (sel) {
        case 0: h = g_xh;    l = g_xl;    break;
        case 1: h = g_Wh[0]; l = g_Wl[0]; break;
        case 2: h = g_Wh[1]; l = g_Wl[1]; break;
        case 3: h = g_Wh[2]; l = g_Wl[2]; break;
        default:h = g_Wh[3]; l = g_Wl[3]; break;
    }
    int i = (blockIdx.x*blockDim.x + threadIdx.x) * 4;
    if (i >= n) return;
    float4 v = *(const float4*)(s + i);
    uint32_t h0 = cvt2(v.x, v.y), h1 = cvt2(v.z, v.w);
    uint32_t l0 = cvt2res(v.x, v.y, h0), l1 = cvt2res(v.z, v.w, h1);
    *(uint2*)(h + i) = make_uint2(h0, h1);
    *(uint2*)(l + i) = make_uint2(l0, l1);
}

// =============== bf16 pre-split GEMM core ===============
// CTA 128x128, 8 warps (4m x 2n), warp 32x64. K-chunk 64, double-buffered cp.async.
// Stage tiles (144B row stride, 128 rows): Ah@0 Al@18432 Bh@36864 Bl@55296; stage=73728B.
#define GST  73728u
#define G_AL 18432u
#define G_BH 36864u
#define G_BL 55296u

__device__ __forceinline__ void gemm_load_stage(
    uint32_t stg, const __nv_bfloat16* Ah, const __nv_bfloat16* Al,
    const __nv_bfloat16* Bh, const __nv_bfloat16* Bl, int koff, int tid)
{
    #pragma unroll
    for (int i = 0; i < 4; i++) {
        int idx = tid + i*256;
        int r = idx >> 3, cb = idx & 7;
        uint32_t dst = stg + (uint32_t)r*144u + (uint32_t)cb*16u;
        size_t src = (size_t)r*D_MODEL + koff + cb*8;
        CP16(dst,          Ah + src);
        CP16(dst + G_AL,   Al + src);
        CP16(dst + G_BH,   Bh + src);
        CP16(dst + G_BL,   Bl + src);
    }
}

__device__ __forceinline__ void bf16_gemm_core2(
    const __nv_bfloat16* __restrict__ Ah, const __nv_bfloat16* __restrict__ Al,
    const __nv_bfloat16* __restrict__ Bh, const __nv_bfloat16* __restrict__ Bl,
    char* sm, int tid, float acc[2][8][4])
{
    const int lane = tid & 31, warp = tid >> 5;
    const int wm = warp & 3, wn = warp >> 2;
    const uint32_t sb = smem_u32(sm);
    const uint32_t a_off = (uint32_t)(wm*32 + (lane & 15))*144u + (uint32_t)((lane >> 4)*16);
    const uint32_t b_off = (uint32_t)(wn*64 + (lane & 7) + ((lane >> 4)*8))*144u
                         + (uint32_t)(((lane >> 3) & 1)*16);

    #pragma unroll
    for (int mt = 0; mt < 2; mt++)
        #pragma unroll
        for (int nt = 0; nt < 8; nt++)
            #pragma unroll
            for (int q = 0; q < 4; q++) acc[mt][nt][q] = 0.f;

    gemm_load_stage(sb, Ah, Al, Bh, Bl, 0, tid);
    CPC();

    for (int c = 0; c < 16; c++) {
        if (c < 15) {
            gemm_load_stage(sb + ((c+1) & 1)*GST, Ah, Al, Bh, Bl, (c+1)*64, tid);
            CPC();
            CPW(1);
        } else {
            CPW(0);
        }
        __syncthreads();

        const uint32_t stg = sb + (c & 1)*GST;
        #pragma unroll
        for (int kc = 0; kc < 4; kc++) {
            uint32_t aH[2][4], aL[2][4];
            ldsm4(aH[0], stg + a_off + kc*32);
            ldsm4(aH[1], stg + a_off + 16*144 + kc*32);
            ldsm4(aL[0], stg + G_AL + a_off + kc*32);
            ldsm4(aL[1], stg + G_AL + a_off + 16*144 + kc*32);
            uint32_t bH[4][4], bL[4][4];
            #pragma unroll
            for (int g = 0; g < 4; g++) {
                ldsm4(bH[g], stg + G_BH + b_off + g*2304u + kc*32);
                ldsm4(bL[g], stg + G_BL + b_off + g*2304u + kc*32);
            }
            #pragma unroll
            for (int mt = 0; mt < 2; mt++)
                #pragma unroll
                for (int nt = 0; nt < 8; nt++) {
                    uint32_t b0 = bH[nt>>1][(nt&1)*2], b1 = bH[nt>>1][(nt&1)*2+1];
                    uint32_t c0 = bL[nt>>1][(nt&1)*2], c1 = bL[nt>>1][(nt&1)*2+1];
                    mma16816(acc[mt][nt], aH[mt], b0, b1);
                    mma16816(acc[mt][nt], aL[mt], b0, b1);
                    mma16816(acc[mt][nt], aH[mt], c0, c1);
                }
        }
        __syncthreads();
    }
}

// =============== fused QKV GEMM + RoPE + bf16-split store ===============
__global__ __launch_bounds__(256) void tc_qkv_kernel()
{
    extern __shared__ char sm[];
    const int tid = threadIdx.x;
    const int z = blockIdx.z;
    const int m0 = blockIdx.y * 128;
    const int n0 = blockIdx.x * 128;

    float acc[2][8][4];
    bf16_gemm_core2(g_xh + (size_t)m0*D_MODEL, g_xl + (size_t)m0*D_MODEL,
                    g_Wh[z] + (size_t)n0*D_MODEL, g_Wl[z] + (size_t)n0*D_MODEL,
                    sm, tid, acc);

    const int lane = tid & 31, warp = tid >> 5;
    const int wm = warp & 3, wn = warp >> 2;

    #pragma unroll
    for (int mt = 0; mt < 2; mt++) {
        #pragma unroll
        for (int rr = 0; rr < 2; rr++) {
            int m = m0 + wm*32 + mt*16 + (lane >> 2) + rr*8;
            int b = m >> 11, s = m & (SEQ-1);
            int bh = b*NHEADS;
            #pragma unroll
            for (int nt = 0; nt < 8; nt++) {
                int n = n0 + wn*64 + nt*8 + (lane & 3)*2;
                int h = n >> 6, d = n & 63;
                float x1 = acc[mt][nt][rr*2], x2 = acc[mt][nt][rr*2+1];
                if (z < 2) {
                    float cv = g_cos[s*(DK/2) + (d >> 1)];
                    float sv = g_sin[s*(DK/2) + (d >> 1)];
                    float o1 = cv*x1 - sv*x2;
                    float o2 = sv*x1 + cv*x2;
                    uint32_t hv = cvt2(o1, o2);
                    uint32_t lv = cvt2res(o1, o2, hv);
                    size_t base = ((size_t)(bh + h)*SEQ + s)*DK + d;
                    if (z == 0) {
                        *(uint32_t*)(g_Qh + base) = hv;
                        *(uint32_t*)(g_Ql + base) = lv;
                    } else {
                        *(uint32_t*)(g_Kh + base) = hv;
                        *(uint32_t*)(g_Kl + base) = lv;
                    }
                } else {
                    size_t tb = ((size_t)(bh + h)*DK + d)*SEQ + s;
                    __nv_bfloat16 h1 = __float2bfloat16_rn(x1);
                    __nv_bfloat16 h2 = __float2bfloat16_rn(x2);
                    g_Vth[tb]       = h1;
                    g_Vth[tb + SEQ] = h2;
                    g_Vtl[tb]       = __float2bfloat16_rn(x1 - __bfloat162float(h1));
                    g_Vtl[tb + SEQ] = __float2bfloat16_rn(x2 - __bfloat162float(h2));
                }
            }
        }
    }
}

// =============== output projection ===============
__global__ __launch_bounds__(256) void tc_out_kernel(float* __restrict__ out)
{
    extern __shared__ char sm[];
    const int tid = threadIdx.x;
    const int m0 = blockIdx.y * 128;
    const int n0 = blockIdx.x * 128;

    float acc[2][8][4];
    bf16_gemm_core2(g_Ah + (size_t)m0*D_MODEL, g_Al + (size_t)m0*D_MODEL,
                    g_Wh[3] + (size_t)n0*D_MODEL, g_Wl[3] + (size_t)n0*D_MODEL,
                    sm, tid, acc);

    const int lane = tid & 31, warp = tid >> 5;
    const int wm = warp & 3, wn = warp >> 2;

    #pragma unroll
    for (int mt = 0; mt < 2; mt++) {
        #pragma unroll
        for (int rr = 0; rr < 2; rr++) {
            int m = m0 + wm*32 + mt*16 + (lane >> 2) + rr*8;
            #pragma unroll
            for (int nt = 0; nt < 8; nt++) {
                int n = n0 + wn*64 + nt*8 + (lane & 3)*2;
                *(float2*)(out + (size_t)m*D_MODEL + n) =
                    make_float2(acc[mt][nt][rr*2], acc[mt][nt][rr*2+1]);
            }
        }
    }
}

// =============== flash attention (HMMA bf16 3-split, R6-proven) ===============
#define FSTG 36864u

__global__ __launch_bounds__(256,1) void flash_kernel()
{
    extern __shared__ char sm[];
    const uint32_t sb = smem_u32(sm);
    const int tid = threadIdx.x;
    const int lane = tid & 31, w = tid >> 5;
    const int qt = gridDim.x - 1 - (int)blockIdx.x;
    const int bh = blockIdx.y;
    const int b = bh >> 4, h = bh & 15;

    const __nv_bfloat16* Qhg = g_Qh + (size_t)bh*SEQ*DK + (size_t)qt*128*DK;
    const __nv_bfloat16* Qlg = g_Ql + (size_t)bh*SEQ*DK + (size_t)qt*128*DK;
    const __nv_bfloat16* Khg = g_Kh + (size_t)bh*SEQ*DK;
    const __nv_bfloat16* Klg = g_Kl + (size_t)bh*SEQ*DK;
    const __nv_bfloat16* Vhg = g_Vth + (size_t)bh*DK*SEQ;
    const __nv_bfloat16* Vlg = g_Vtl + (size_t)bh*DK*SEQ;

    const uint32_t QH = sb + 2*FSTG, QL = QH + 18432u;

    #pragma unroll
    for (int i = 0; i < 4; i++) {
        int idx = tid + i*256;
        int r = idx >> 3, c = idx & 7;
        CP16(QH + r*144 + c*16, Qhg + r*64 + c*8);
        CP16(QL + r*144 + c*16, Qlg + r*64 + c*8);
    }
    CPC();
    #pragma unroll
    for (int i = 0; i < 2; i++) {
        int idx = tid + i*256;
        int r = idx >> 3, c = idx & 7;
        CP16(sb + r*144 + c*16,           Khg + r*64 + c*8);
        CP16(sb + 9216u + r*144 + c*16,   Klg + r*64 + c*8);
        CP16(sb + 18432u + r*144 + c*16,  Vhg + (size_t)r*SEQ + c*8);
        CP16(sb + 27648u + r*144 + c*16,  Vlg + (size_t)r*SEQ + c*8);
    }
    CPC();
    CPW(1);
    __syncthreads();

    uint32_t qfh[4][4], qfl[4][4];
    const uint32_t a_off = (uint32_t)((w*16 + (lane & 15))*144) + (uint32_t)((lane >> 4)*16);
    #pragma unroll
    for (int kc = 0; kc < 4; kc++) {
        ldsm4(qfh[kc], QH + a_off + kc*32);
        ldsm4(qfl[kc], QL + a_off + kc*32);
    }

    const uint32_t b_off = (uint32_t)(((lane & 7) + ((lane >> 4)*8))*144)
                         + (uint32_t)(((lane >> 3) & 1)*16);

    float o[8][4];
    #pragma unroll
    for (int dt = 0; dt < 8; dt++)
        #pragma unroll
        for (int q = 0; q < 4; q++) o[dt][q] = 0.f;
    float m0 = -1e30f, m1 = -1e30f, l0 = 0.f, l1 = 0.f;
    const float SC = 0.18033688011112042f;
    const int ktmax = 2*qt + 1;

    for (int kt = 0; kt <= ktmax; kt++) {
        if (kt < ktmax) {
            uint32_t st = sb + ((kt+1) & 1)*FSTG;
            const __nv_bfloat16* kh = Khg + (size_t)(kt+1)*64*DK;
            const __nv_bfloat16* kl = Klg + (size_t)(kt+1)*64*DK;
            #pragma unroll
            for (int i = 0; i < 2; i++) {
                int idx = tid + i*256;
                int r = idx >> 3, c = idx & 7;
                CP16(st + r*144 + c*16,          kh + r*64 + c*8);
                CP16(st + 9216u + r*144 + c*16,  kl + r*64 + c*8);
                CP16(st + 18432u + r*144 + c*16, Vhg + (size_t)r*SEQ + (kt+1)*64 + c*8);
                CP16(st + 27648u + r*144 + c*16, Vlg + (size_t)r*SEQ + (kt+1)*64 + c*8);
            }
            CPC();
            CPW(1);
        } else {
            CPW(0);
        }
        __syncthreads();

        const uint32_t st = sb + (kt & 1)*FSTG;

        float acc[8][4];
        #pragma unroll
        for (int nt = 0; nt < 8; nt++)
            #pragma unroll
            for (int q = 0; q < 4; q++) acc[nt][q] = 0.f;

        #pragma unroll
        for (int kc = 0; kc < 4; kc++) {
            uint32_t kbh[4][4], kbl[4][4];
            #pragma unroll
            for (int g = 0; g < 4; g++) {
                ldsm4(kbh[g], st + b_off + g*2304u + kc*32);
                ldsm4(kbl[g], st + 9216u + b_off + g*2304u + kc*32);
            }
            #pragma unroll
            for (int nt = 0; nt < 8; nt++) {
                uint32_t b0 = kbh[nt>>1][(nt&1)*2], b1 = kbh[nt>>1][(nt&1)*2+1];
                uint32_t c0 = kbl[nt>>1][(nt&1)*2], c1 = kbl[nt>>1][(nt&1)*2+1];
                mma16816(acc[nt], qfh[kc], b0, b1);
                mma16816(acc[nt], qfl[kc], b0, b1);
                mma16816(acc[nt], qfh[kc], c0, c1);
            }
        }

        if (kt >= 2*qt) {
            #pragma unroll
            for (int nt = 0; nt < 8; nt++)
                #pragma unroll
                for (int j = 0; j < 4; j++) {
                    int kj = kt*64 + nt*8 + ((lane & 3) << 1) + (j & 1);
                    int qi = qt*128 + w*16 + (lane >> 2) + ((j >> 1) << 3);
                    acc[nt][j] = (kj <= qi) ? acc[nt][j]*SC : -1e30f;
                }
        } else {
            #pragma unroll
            for (int nt = 0; nt < 8; nt++)
                #pragma unroll
                for (int j = 0; j < 4; j++) acc[nt][j] *= SC;
        }

        float mx0 = -1e30f, mx1 = -1e30f;
        #pragma unroll
        for (int nt = 0; nt < 8; nt++) {
            mx0 = fmaxf(mx0, fmaxf(acc[nt][0], acc[nt][1]));
            mx1 = fmaxf(mx1, fmaxf(acc[nt][2], acc[nt][3]));
        }
        mx0 = fmaxf(mx0, __shfl_xor_sync(0xffffffffu, mx0, 1));
        mx0 = fmaxf(mx0, __shfl_xor_sync(0xffffffffu, mx0, 2));
        mx1 = fmaxf(mx1, __shfl_xor_sync(0xffffffffu, mx1, 1));
        mx1 = fmaxf(mx1, __shfl_xor_sync(0xffffffffu, mx1, 2));
        float mn0 = fmaxf(m0, mx0), mn1 = fmaxf(m1, mx1);
        float rs0 = 0.f, rs1 = 0.f;
        #pragma unroll
        for (int nt = 0; nt < 8; nt++) {
            acc[nt][0] = exp2f_fast(acc[nt][0] - mn0);
            acc[nt][1] = exp2f_fast(acc[nt][1] - mn0);
            acc[nt][2] = exp2f_fast(acc[nt][2] - mn1);
            acc[nt][3] = exp2f_fast(acc[nt][3] - mn1);
            rs0 += acc[nt][0] + acc[nt][1];
            rs1 += acc[nt][2] + acc[nt][3];
        }
        rs0 += __shfl_xor_sync(0xffffffffu, rs0, 1);
        rs0 += __shfl_xor_sync(0xffffffffu, rs0, 2);
        rs1 += __shfl_xor_sync(0xffffffffu, rs1, 1);
        rs1 += __shfl_xor_sync(0xffffffffu, rs1, 2);
        float corr0 = exp2f_fast(m0 - mn0);
        float corr1 = exp2f_fast(m1 - mn1);
        l0 = l0*corr0 + rs0;  m0 = mn0;
        l1 = l1*corr1 + rs1;  m1 = mn1;
        #pragma unroll
        for (int dt = 0; dt < 8; dt++) {
            o[dt][0] *= corr0; o[dt][1] *= corr0;
            o[dt][2] *= corr1; o[dt][3] *= corr1;
        }

        #pragma unroll
        for (int kc = 0; kc < 4; kc++) {
            uint32_t pah[4], pal[4];
            pah[0] = cvt2(acc[2*kc][0],   acc[2*kc][1]);   pal[0] = cvt2res(acc[2*kc][0],   acc[2*kc][1],   pah[0]);
            pah[1] = cvt2(acc[2*kc][2],   acc[2*kc][3]);   pal[1] = cvt2res(acc[2*kc][2],   acc[2*kc][3],   pah[1]);
            pah[2] = cvt2(acc[2*kc+1][0], acc[2*kc+1][1]); pal[2] = cvt2res(acc[2*kc+1][0], acc[2*kc+1][1], pah[2]);
            pah[3] = cvt2(acc[2*kc+1][2], acc[2*kc+1][3]); pal[3] = cvt2res(acc[2*kc+1][2], acc[2*kc+1][3], pah[3]);
            uint32_t vbh[4][4], vbl[4][4];
            #pragma unroll
            for (int g = 0; g < 4; g++) {
                ldsm4(vbh[g], st + 18432u + b_off + g*2304u + kc*32);
                ldsm4(vbl[g], st + 27648u + b_off + g*2304u + kc*32);
            }
            #pragma unroll
            for (int dt = 0; dt < 8; dt++) {
                uint32_t b0 = vbh[dt>>1][(dt&1)*2], b1 = vbh[dt>>1][(dt&1)*2+1];
                uint32_t c0 = vbl[dt>>1][(dt&1)*2], c1 = vbl[dt>>1][(dt&1)*2+1];
                mma16816(o[dt], pah, b0, b1);
                mma16816(o[dt], pal, b0, b1);
                mma16816(o[dt], pah, c0, c1);
            }
        }
        __syncthreads();
    }

    // ---- epilogue: normalize, write bf16 h/l split to g_Ah/g_Al [B,S,D_MODEL] ----
    float inv0 = 1.0f / l0, inv1 = 1.0f / l1;
    int r0 = qt*128 + w*16 + (lane >> 2);
    #pragma unroll
    for (int dt = 0; dt < 8; dt++) {
        int d = dt*8 + (lane & 3)*2;
        size_t p0 = ((size_t)b*SEQ + r0)*D_MODEL + h*64 + d;
        size_t p1 = p0 + (size_t)8*D_MODEL;
        float a0 = o[dt][0]*inv0, a1 = o[dt][1]*inv0;
        float a2 = o[dt][2]*inv1, a3 = o[dt][3]*inv1;
        uint32_t h0 = cvt2(a0, a1), h1v = cvt2(a2, a3);
        *(uint32_t*)(g_Ah + p0) = h0;
        *(uint32_t*)(g_Al + p0) = cvt2res(a0, a1, h0);
        *(uint32_t*)(g_Ah + p1) = h1v;
        *(uint32_t*)(g_Al + p1) = cvt2res(a2, a3, h1v);
    }
}

// ---------------- launch ----------------
extern "C" void kernel_launch(void* const* d_in, const int* in_sizes, int n_in,
                              void* d_out, int out_size)
{
    const float* x  = (const float*)d_in[0];
    const float* Wq = (const float*)d_in[1];
    const float* Wk = (const float*)d_in[2];
    const float* Wv = (const float*)d_in[3];
    const float* Wo = (const float*)d_in[4];
    float* out = (float*)d_out;

    const int gemm_smem  = 2*GST;                    // 147456 B
    const int flash_smem = 2*FSTG + 2*18432;         // 110592 B
    cudaFuncSetAttribute(tc_qkv_kernel, cudaFuncAttributeMaxDynamicSharedMemorySize, gemm_smem);
    cudaFuncSetAttribute(tc_out_kernel, cudaFuncAttributeMaxDynamicSharedMemorySize, gemm_smem);
    cudaFuncSetAttribute(flash_kernel,  cudaFuncAttributeMaxDynamicSharedMemorySize, flash_smem);

    rope_table_kernel<<<(SEQ*(DK/2) + 255)/256, 256>>>();

    const int NX = MTOT*D_MODEL, NW = D_MODEL*D_MODEL;
    split_kernel<<<(NX/4 + 255)/256, 256>>>(x,  0, NX);
    split_kernel<<<(NW/4 + 255)/256, 256>>>(Wq, 1, NW);
    split_kernel<<<(NW/4 + 255)/256, 256>>>(Wk, 2, NW);
    split_kernel<<<(NW/4 + 255)/256, 256>>>(Wv, 3, NW);
    split_kernel<<<(NW/4 + 255)/256, 256>>>(Wo, 4, NW);

    dim3 g1(D_MODEL/128, MTOT/128, 3);
    tc_qkv_kernel<<<g1, 256, gemm_smem>>>();

    dim3 g2(SEQ/128, NBH);
    flash_kernel<<<g2, 256, flash_smem>>>();

    dim3 g3(D_MODEL/128, MTOT/128);
    tc_out_kernel<<<g3, 256, gemm_smem>>>(out);
}